// round 17
// baseline (speedup 1.0000x reference)
#include <cuda_runtime.h>
#include <cuda_bf16.h>

// Problem constants (fixed shapes: x = (8,3,1024,1024) fp32, patch_size=24, stride=16)
namespace {
constexpr int Hh  = 1024;
constexpr int Ww  = 1024;
constexpr int Bb  = 8;
constexpr int Cc  = 3;
constexpr int PS  = 24;   // patch size
constexpr int ST  = 16;   // stride
constexpr int Mm  = 4;    // (PS - ST) / 2 reflect pad
constexpr int NH  = 64;   // 1024 / 16
constexpr int NW  = 64;
constexpr int ROWLEN = Ww + 2 * Mm;              // 1032 padded row
constexpr int THREADS = 384;
constexpr int PATCH_F4 = (PS * PS * Cc) / 4;     // 432 float4 per patch
constexpr long long MAIN_SZ = (long long)Bb * NH * NW * PS * PS * Cc; // 56,623,104
}

// One block = one (b, i, r-pair): TWO padded source rows feed all 64 patches
// of patch-row i at within-patch rows 2*rx and 2*rx+1.
//
// Load phase: 512 transpose-units (2 rows x 256 float4 col-groups). Each unit
// reads the same float4 col-group from all 3 channel planes (coalesced
// LDG.128 x3), permutes in registers to channel-interleaved order, and writes
// 3 STS.128 at float offset 12+12g — lane stride 12 words at float4 granule
// covers all 32 banks exactly once per phase: CONFLICT-FREE (R15's scalar
// channel-strided STS.32 had 4-way conflicts; that was the 71.7% L1 pipe).
//
// Shared memory holds each row CHANNEL-INTERLEAVED: sI[row][col*3 + ch].
// Patch j's 72-float run covers floats 48j..48j+71 — contiguous, 16B-aligned
// at every float4 boundary, so emit is pure LDS.128 -> STG.128 (via __stcs:
// output is write-once; keep the input resident in L2).
__global__ __launch_bounds__(THREADS, 5)
void patcher_kernel(const float* __restrict__ x, float4* __restrict__ out,
                    float* __restrict__ extras, int n_extra)
{
    __shared__ float sI[2][Cc * ROWLEN];   // 2 x 12384 B

    const int rx = blockIdx.x;  // 0..11  row-pair
    const int i  = blockIdx.y;  // 0..63  patch row
    const int b  = blockIdx.z;  // 0..7   batch
    const int t  = threadIdx.x;

    // fused trailing (nH, nW) write — one designated block
    if (rx == 0 && i == 0 && b == 0 && t < n_extra) {
        extras[t] = 64.0f;   // nH = nW = 64
    }

    // two source rows with reflect padding (reflect w/o edge repeat)
    int vrow[2];
    #pragma unroll
    for (int rr = 0; rr < 2; ++rr) {
        int v = i * ST + (2 * rx + rr) - Mm;
        v = (v < 0) ? -v : v;
        v = (v > Hh - 1) ? 2 * (Hh - 1) - v : v;
        vrow[rr] = v;
    }

    const size_t plane = (size_t)Hh * Ww;
    const float* base = x + (size_t)b * Cc * plane;

    // ---- main loads: 512 units, register transpose, conflict-free STS.128 ----
    #pragma unroll
    for (int it = 0; it < 2; ++it) {
        int u = t + it * THREADS;          // 0..767 (active only u < 512)
        if (u < 512) {
            int rr = u >> 8;               // 0..1  row within pair
            int g  = u & 255;              // float4 col-group
            const float* rp = base + (size_t)vrow[rr] * Ww;
            float4 a = reinterpret_cast<const float4*>(rp)[g];              // ch0
            float4 bb4 = reinterpret_cast<const float4*>(rp + plane)[g];    // ch1
            float4 c = reinterpret_cast<const float4*>(rp + 2 * plane)[g];  // ch2

            // interleaved run for padded cols Mm+4g..Mm+4g+3:
            // [a0 b0 c0 a1 | b1 c1 a2 b2 | c2 a3 b3 c3]
            float* dst = &sI[rr][(Mm + 4 * g) * Cc];  // float off 12+12g, 16B-aligned
            reinterpret_cast<float4*>(dst)[0] = make_float4(a.x, bb4.x, c.x, a.y);
            reinterpret_cast<float4*>(dst)[1] = make_float4(bb4.y, c.y, a.z, bb4.z);
            reinterpret_cast<float4*>(dst)[2] = make_float4(c.z, a.w, bb4.w, c.w);
        }
    }

    // ---- reflect halo columns: 2 rows x 3 ch x 8 = 48 threads ----
    // (uses threads 128..175: idle in load iteration 1, spreads LSU work)
    if (t >= 128 && t < 176) {
        int t1 = t - 128;
        int rr = t1 / 24;
        int t2 = t1 - rr * 24;
        int ch = t2 >> 3;
        int p  = t2 & 7;
        const float* rowp = base + (size_t)ch * plane + (size_t)vrow[rr] * Ww;
        if (p < 4) {
            // padded col s = 3-p  <=>  orig col -(p+1) -> reflect -> col p+1
            sI[rr][(3 - p) * Cc + ch] = rowp[p + 1];
        } else {
            int k = p - 3;  // 1..4 ; padded col 1027+k <=> orig 1023+k -> 1023-k
            sI[rr][(Mm + (Ww - 1) + k) * Cc + ch] = rowp[(Ww - 1) - k];
        }
    }
    __syncthreads();

    // ---- emit: out[((b*64+i)*64 + j)*432 + r*18 + t18] (float4 units) ----
    const size_t baseBI = ((size_t)(b * NH + i) * NW) * PATCH_F4;

    #pragma unroll
    for (int it = 0; it < 3; ++it) {
        int q   = t + it * THREADS;     // 0..1151
        int j   = q / 18;               // patch column 0..63
        int t18 = q - j * 18;           // float4 index inside the 72-float run
        size_t o = baseBI + (size_t)j * PATCH_F4 + t18;

        #pragma unroll
        for (int rr = 0; rr < 2; ++rr) {
            // patch j run starts at padded col 16j -> float 48j -> float4 12j
            float4 val = reinterpret_cast<const float4*>(sI[rr])[12 * j + t18];
            __stcs(&out[o + (size_t)(2 * rx + rr) * 18], val);
        }
    }
}

extern "C" void kernel_launch(void* const* d_in, const int* in_sizes, int n_in,
                              void* d_out, int out_size)
{
    const float* x = (const float*)d_in[0];
    float* out = (float*)d_out;

    long long extra = (long long)out_size - MAIN_SZ;
    int n_extra = extra > 0 ? (int)extra : 0;

    dim3 grid(PS / 2, NH, Bb);  // (12, 64, 8) = 6144 blocks
    patcher_kernel<<<grid, THREADS>>>(x, reinterpret_cast<float4*>(out),
                                      out + MAIN_SZ, n_extra);
}